// round 11
// baseline (speedup 1.0000x reference)
#include <cuda_runtime.h>
#include <cuda_bf16.h>
#include <cstdint>

#define NPTS 8            // points per CTA
#define MROWS 48          // 8 points x 6 channels
#define TPB 256           // 8 warps

// ---- SMEM layout (byte offsets from 1024-aligned base) ----
#define ASTR    528       // A row stride bytes (264 halves; 256 used + pad)
#define OFF_AHI 0         // 48*528 = 25344
#define OFF_ALO 25344     // ends 50688
#define OFF_B   50688     // 3 x chunk buffers of 16896 B (2 splits x 16 k-rows x 528 B)
#define BUF_BYTES 16896
#define BSPL    8448      // split offset inside a chunk buffer (16*528)
#define BSTR    528
#define OFF_SCR 50688     // fp32 scratch [48][260] = 49920 — ALIASES buffers (temporally disjoint)
#define SCRSTR  260
#define SMEM_BYTES (50688 + 3 * 16896 + 1024)   // 102400

// pre-split weights (hi/lo bf16), [3 layers][256 k][256 n]
__device__ __align__(16) __nv_bfloat16 g_Whi[3 * 256 * 256];
__device__ __align__(16) __nv_bfloat16 g_Wlo[3 * 256 * 256];

#define LDSM4(R0,R1,R2,R3,ADDR) \
  asm volatile("ldmatrix.sync.aligned.m8n8.x4.shared.b16 {%0,%1,%2,%3}, [%4];" \
    : "=r"(R0),"=r"(R1),"=r"(R2),"=r"(R3) : "r"(ADDR))
#define LDSM4T(R0,R1,R2,R3,ADDR) \
  asm volatile("ldmatrix.sync.aligned.m8n8.x4.trans.shared.b16 {%0,%1,%2,%3}, [%4];" \
    : "=r"(R0),"=r"(R1),"=r"(R2),"=r"(R3) : "r"(ADDR))
#define MMA_BF16(D,A0,A1,A2,A3,B0,B1) \
  asm volatile("mma.sync.aligned.m16n8k16.row.col.f32.bf16.bf16.f32 " \
    "{%0,%1,%2,%3},{%4,%5,%6,%7},{%8,%9},{%0,%1,%2,%3};" \
    : "+f"(D[0]),"+f"(D[1]),"+f"(D[2]),"+f"(D[3]) \
    : "r"(A0),"r"(A1),"r"(A2),"r"(A3),"r"(B0),"r"(B1))
#define CP16(S,G) asm volatile("cp.async.cg.shared.global [%0], [%1], 16;" :: "r"(S), "l"(G))
#define CP_COMMIT() asm volatile("cp.async.commit_group;" ::: "memory")
#define CP_WAIT1() asm volatile("cp.async.wait_group 1;" ::: "memory")
#define CP_WAIT0() asm volatile("cp.async.wait_group 0;" ::: "memory")

__device__ __forceinline__ uint32_t smem_u32(const void* p) {
    uint32_t a;
    asm("{ .reg .u64 t; cvta.to.shared.u64 t, %1; cvt.u32.u64 %0, t; }" : "=r"(a) : "l"(p));
    return a;
}

__device__ __forceinline__ void swish_derivs(float z, float& s, float& sp, float& spp) {
    float sig = 1.0f / (1.0f + __expf(-z));
    float om  = 1.0f - sig;
    s   = z * sig;
    sp  = sig * (1.0f + z * om);
    spp = sig * om * (2.0f + z * (1.0f - 2.0f * sig));
}

// write value as bf16 hi/lo into A buffers; row-major, 528B row stride
__device__ __forceinline__ void storeA(char* sm, int row, int k, float v) {
    const uint32_t o = (uint32_t)row * ASTR + (uint32_t)k * 2;
    __nv_bfloat16 hi = __float2bfloat16(v);
    float rem = v - __bfloat162float(hi);
    __nv_bfloat16 lo = __float2bfloat16(rem);
    *reinterpret_cast<__nv_bfloat16*>(sm + OFF_AHI + o) = hi;
    *reinterpret_cast<__nv_bfloat16*>(sm + OFF_ALO + o) = lo;
}

// ---- prep: split W1..W3 into bf16 hi/lo ----
__global__ void prep_kernel(const float* __restrict__ W1, const float* __restrict__ W2,
                            const float* __restrict__ W3) {
    int i = blockIdx.x * blockDim.x + threadIdx.x;
    if (i >= 3 * 65536) return;
    const int layer = i >> 16;
    const int r = i & 65535;
    const float* W = (layer == 0) ? W1 : (layer == 1) ? W2 : W3;
    const float w = W[r];
    __nv_bfloat16 hi = __float2bfloat16(w);
    float rem = w - __bfloat162float(hi);
    g_Whi[i] = hi;
    g_Wlo[i] = __float2bfloat16(rem);
}

// prefetch chunk c (16 k-rows, both splits) of layer L into buffer b via cp.async
// 1024 uint4 total = 256 threads x 4
__device__ __forceinline__ void prefetch_chunk(uint32_t sbase, int tid, int L, int c, int b) {
    const uint32_t dbase = sbase + OFF_B + (uint32_t)b * BUF_BYTES;
    #pragma unroll
    for (int it = 0; it < 4; it++) {
        const int i = tid + it * TPB;
        const int split = i >> 9;
        const int rem = i & 511;
        const int r = rem >> 5;
        const int cc = rem & 31;
        const char* g = split ? (const char*)g_Wlo : (const char*)g_Whi;
        const char* src = g + (size_t)L * 131072 + (size_t)(c * 16 + r) * 512 + (size_t)cc * 16;
        const uint32_t dst = dbase + (uint32_t)split * BSPL + (uint32_t)r * BSTR + (uint32_t)cc * 16;
        CP16(dst, src);
    }
}

// ---- main kernel ----
__global__ __launch_bounds__(TPB, 2)
void pinn_mma_kernel(
    const float* __restrict__ x, const float* __restrict__ y,
    const float* __restrict__ t, const float* __restrict__ nu,
    const float* __restrict__ W0, const float* __restrict__ b0,
    const float* __restrict__ b1, const float* __restrict__ b2,
    const float* __restrict__ b3,
    const float* __restrict__ W4, const float* __restrict__ b4,
    float* __restrict__ out, int N)
{
    extern __shared__ char smem_raw[];
    const uint32_t rawa = smem_u32(smem_raw);
    const uint32_t sbase = (rawa + 1023u) & ~1023u;
    char* sm = smem_raw + (sbase - rawa);
    float* scr = reinterpret_cast<float*>(sm + OFF_SCR);   // [48][260], aliases buffers

    const int tid  = threadIdx.x;
    const int wid  = tid >> 5;       // 0..7
    const int lane = tid & 31;
    const int base = blockIdx.x * NPTS;

    const int n0 = wid * 32;         // N group start (32 cols per warp)
    const int nn = tid;              // neuron for layer0/epilogue (0..255)

    // prefetch layer-0 weight chunks behind the scalar layer-0 phase
    prefetch_chunk(sbase, tid, 0, 0, 0); CP_COMMIT();
    prefetch_chunk(sbase, tid, 0, 1, 1); CP_COMMIT();

    // ---------------- layer 0: (4 -> 256) scalar -> A hi/lo -----------------
    {
        const float w0 = W0[nn], w1 = W0[256 + nn], w2 = W0[512 + nn], w3 = W0[768 + nn];
        const float bb = b0[nn];
        #pragma unroll 1
        for (int p = 0; p < NPTS; p++) {
            int idx = base + p; if (idx >= N) idx = N - 1;
            const float xs = x[idx];
            const float ys = y[idx];
            const float ts = 2.0f * t[idx] - 1.0f;
            const float ns = 2.0f * (nu[idx] - 0.01f) * (1.0f / 0.09f) - 1.0f;
            const float z  = fmaf(xs, w0, fmaf(ys, w1, fmaf(ts, w2, fmaf(ns, w3, bb))));
            const float zx = w0, zy = w1, zt = 2.0f * w2;
            float s, sp, spp; swish_derivs(z, s, sp, spp);
            const int rb = p * 6;
            storeA(sm, rb + 0, nn, s);
            storeA(sm, rb + 1, nn, sp * zx);
            storeA(sm, rb + 2, nn, sp * zy);
            storeA(sm, rb + 3, nn, sp * zt);
            storeA(sm, rb + 4, nn, spp * zx * zx);
            storeA(sm, rb + 5, nn, spp * zy * zy);
        }
    }
    __syncthreads();

    // ---------------- 3 hidden layers: bf16-split GEMM + swish --------------
    #pragma unroll 1
    for (int L = 0; L < 3; L++) {
        const float* __restrict__ bptr = (L == 0) ? b1 : (L == 1) ? b2 : b3;

        float acc[3][4][4];   // [m-tile][n-tile(8 cols)][frag]
        #pragma unroll
        for (int m = 0; m < 3; m++)
            #pragma unroll
            for (int nt = 0; nt < 4; nt++)
                #pragma unroll
                for (int r = 0; r < 4; r++) acc[m][nt][r] = 0.0f;

        if (L > 0) {
            prefetch_chunk(sbase, tid, L, 0, 0); CP_COMMIT();
            prefetch_chunk(sbase, tid, L, 1, 1); CP_COMMIT();
        }

        #pragma unroll 1
        for (int c = 0; c < 16; c++) {
            if (c < 15) { CP_WAIT1(); } else { CP_WAIT0(); }
            __syncthreads();                       // chunk c visible; prior buffer readers done
            if (c + 2 < 16) { prefetch_chunk(sbase, tid, L, c + 2, (c + 2) % 3); CP_COMMIT(); }

            const uint32_t bufb = sbase + OFF_B + (uint32_t)(c % 3) * BUF_BYTES;

            // load B fragments once: hi and lo
            uint32_t Bh[8], Bl[8];
            #pragma unroll
            for (int q = 0; q < 2; q++) {
                const uint32_t roff = (uint32_t)(lane & 15) * BSTR
                                    + (uint32_t)(n0 + q * 16 + (lane >> 4) * 8) * 2;
                LDSM4T(Bh[q * 4], Bh[q * 4 + 1], Bh[q * 4 + 2], Bh[q * 4 + 3], bufb + roff);
                LDSM4T(Bl[q * 4], Bl[q * 4 + 1], Bl[q * 4 + 2], Bl[q * 4 + 3], bufb + BSPL + roff);
            }
            // load ALL m-tiles' Ahi fragments up front
            uint32_t Ah[3][4];
            uint32_t aroff[3];
            #pragma unroll
            for (int m = 0; m < 3; m++) {
                aroff[m] = (uint32_t)(m * 16 + (lane & 15)) * ASTR
                         + (uint32_t)(c * 16 + (lane >> 4) * 8) * 2;
                LDSM4(Ah[m][0], Ah[m][1], Ah[m][2], Ah[m][3], sbase + OFF_AHI + aroff[m]);
            }
            // set 1: Ahi x Bhi
            #pragma unroll
            for (int m = 0; m < 3; m++)
                #pragma unroll
                for (int nt = 0; nt < 4; nt++)
                    MMA_BF16(acc[m][nt], Ah[m][0], Ah[m][1], Ah[m][2], Ah[m][3],
                             Bh[nt * 2], Bh[nt * 2 + 1]);
            // set 2: Ahi x Blo
            #pragma unroll
            for (int m = 0; m < 3; m++)
                #pragma unroll
                for (int nt = 0; nt < 4; nt++)
                    MMA_BF16(acc[m][nt], Ah[m][0], Ah[m][1], Ah[m][2], Ah[m][3],
                             Bl[nt * 2], Bl[nt * 2 + 1]);
            // load Alo, set 3: Alo x Bhi
            uint32_t Al[3][4];
            #pragma unroll
            for (int m = 0; m < 3; m++)
                LDSM4(Al[m][0], Al[m][1], Al[m][2], Al[m][3], sbase + OFF_ALO + aroff[m]);
            #pragma unroll
            for (int m = 0; m < 3; m++)
                #pragma unroll
                for (int nt = 0; nt < 4; nt++)
                    MMA_BF16(acc[m][nt], Al[m][0], Al[m][1], Al[m][2], Al[m][3],
                             Bh[nt * 2], Bh[nt * 2 + 1]);
        }
        __syncthreads();   // all MMA buffer reads done; scr (aliased) may now be written

        // ---- epilogue: accums -> scratch -> swish chain -> A hi/lo ----
        #pragma unroll
        for (int m = 0; m < 3; m++) {
            const int row = m * 16 + (lane >> 2);
            #pragma unroll
            for (int nt = 0; nt < 4; nt++) {
                const int col = n0 + nt * 8 + (lane & 3) * 2;
                float* p0 = scr + row * SCRSTR + col;
                p0[0] = acc[m][nt][0];
                p0[1] = acc[m][nt][1];
                float* p1 = p0 + 8 * SCRSTR;
                p1[0] = acc[m][nt][2];
                p1[1] = acc[m][nt][3];
            }
        }
        __syncthreads();

        {
            const float bn = bptr[nn];
            #pragma unroll 1
            for (int p = 0; p < NPTS; p++) {
                const float* zr = scr + (p * 6) * SCRSTR + nn;
                const float z   = zr[0] + bn;
                const float zx  = zr[1 * SCRSTR];
                const float zy  = zr[2 * SCRSTR];
                const float zt  = zr[3 * SCRSTR];
                const float zxx = zr[4 * SCRSTR];
                const float zyy = zr[5 * SCRSTR];
                float s, sp, spp; swish_derivs(z, s, sp, spp);
                const int rb = p * 6;
                storeA(sm, rb + 0, nn, s);
                storeA(sm, rb + 1, nn, sp * zx);
                storeA(sm, rb + 2, nn, sp * zy);
                storeA(sm, rb + 3, nn, sp * zt);
                storeA(sm, rb + 4, nn, fmaf(spp, zx * zx, sp * zxx));
                storeA(sm, rb + 5, nn, fmaf(spp, zy * zy, sp * zyy));
            }
        }
        __syncthreads();
    }

    // ---------------- final layer (256 -> 2) + residual ---------------------
    if (tid < MROWS) {
        const int row = tid;
        float au = 0.0f, av = 0.0f;
        #pragma unroll 1
        for (int i = 0; i < 32; i++) {
            const int k0 = i * 8;
            const uint32_t o = (uint32_t)row * ASTR + (uint32_t)k0 * 2;
            const uint4 vh = *reinterpret_cast<const uint4*>(sm + OFF_AHI + o);
            const uint4 vl = *reinterpret_cast<const uint4*>(sm + OFF_ALO + o);
            const __nv_bfloat16* ph2 = reinterpret_cast<const __nv_bfloat16*>(&vh);
            const __nv_bfloat16* pl2 = reinterpret_cast<const __nv_bfloat16*>(&vl);
            #pragma unroll
            for (int e = 0; e < 8; e++) {
                const float v = __bfloat162float(ph2[e]) + __bfloat162float(pl2[e]);
                const float2 w = *reinterpret_cast<const float2*>(&W4[2 * (k0 + e)]);
                au = fmaf(v, w.x, au);
                av = fmaf(v, w.y, av);
            }
        }
        scr[row * 2 + 0] = au;
        scr[row * 2 + 1] = av;
    }
    __syncthreads();

    if (tid < NPTS) {
        const int idx = base + tid;
        if (idx < N) {
            const int rb = tid * 6;
            const float u   = scr[(rb + 0) * 2 + 0] + b4[0];
            const float v   = scr[(rb + 0) * 2 + 1] + b4[1];
            const float u_x = scr[(rb + 1) * 2 + 0], v_x = scr[(rb + 1) * 2 + 1];
            const float u_y = scr[(rb + 2) * 2 + 0], v_y = scr[(rb + 2) * 2 + 1];
            const float u_t = scr[(rb + 3) * 2 + 0], v_t = scr[(rb + 3) * 2 + 1];
            const float uxx = scr[(rb + 4) * 2 + 0], vxx = scr[(rb + 4) * 2 + 1];
            const float uyy = scr[(rb + 5) * 2 + 0], vyy = scr[(rb + 5) * 2 + 1];
            const float nv = nu[idx];
            out[idx * 2 + 0] = u_t + u * u_x + v * u_y - nv * (uxx + uyy);
            out[idx * 2 + 1] = v_t + u * v_x + v * v_y - nv * (vxx + vyy);
        }
    }
}

extern "C" void kernel_launch(void* const* d_in, const int* in_sizes, int n_in,
                              void* d_out, int out_size) {
    const float* x  = (const float*)d_in[0];
    const float* y  = (const float*)d_in[1];
    const float* t  = (const float*)d_in[2];
    const float* nu = (const float*)d_in[3];
    const float* W0 = (const float*)d_in[4];
    const float* b0 = (const float*)d_in[5];
    const float* W1 = (const float*)d_in[6];
    const float* b1 = (const float*)d_in[7];
    const float* W2 = (const float*)d_in[8];
    const float* b2 = (const float*)d_in[9];
    const float* W3 = (const float*)d_in[10];
    const float* b3 = (const float*)d_in[11];
    const float* W4 = (const float*)d_in[12];
    const float* b4 = (const float*)d_in[13];
    float* out = (float*)d_out;

    const int N = in_sizes[0];

    cudaFuncSetAttribute(pinn_mma_kernel, cudaFuncAttributeMaxDynamicSharedMemorySize, SMEM_BYTES);

    prep_kernel<<<(3 * 65536 + 255) / 256, 256>>>(W1, W2, W3);

    const int blocks = (N + NPTS - 1) / NPTS;
    pinn_mma_kernel<<<blocks, TPB, SMEM_BYTES>>>(x, y, t, nu, W0, b0,
                                                 b1, b2, b3, W4, b4, out, N);
}

// round 12
// speedup vs baseline: 1.1155x; 1.1155x over previous
#include <cuda_runtime.h>
#include <cuda_bf16.h>
#include <cstdint>

#define NPTS 8            // points per CTA
#define MROWS 48          // 8 points x 6 channels
#define TPB 256           // 8 warps

// ---- SMEM layout (byte offsets from 1024-aligned base) ----
#define ASTR    528       // A row stride bytes (264 halves; 256 used + pad)
#define OFF_AHI 0         // 48*528 = 25344
#define OFF_ALO 25344     // ends 50688
#define OFF_B   50688     // 3 x chunk buffers of 16896 B (2 splits x 16 k-rows x 528 B)
#define BUF_BYTES 16896
#define BSPL    8448      // split offset inside a chunk buffer (16*528)
#define BSTR    528
#define OFF_SCR 50688     // fp32 scratch [48][260] = 49920 — ALIASES buffers (temporally disjoint)
#define SCRSTR  260
#define OFF_MBAR 101376   // 3 mbarriers (24 B), after buffers
#define SMEM_BYTES (101376 + 64 + 1024)   // 102464 -> 2 CTAs/SM

// weights staged in EXACT smem-image layout: [layer][chunk16][split2][16 rows x 528B]
__device__ __align__(16) unsigned char g_Wstage[3 * 16 * BUF_BYTES];

#define LDSM4(R0,R1,R2,R3,ADDR) \
  asm volatile("ldmatrix.sync.aligned.m8n8.x4.shared.b16 {%0,%1,%2,%3}, [%4];" \
    : "=r"(R0),"=r"(R1),"=r"(R2),"=r"(R3) : "r"(ADDR))
#define LDSM4T(R0,R1,R2,R3,ADDR) \
  asm volatile("ldmatrix.sync.aligned.m8n8.x4.trans.shared.b16 {%0,%1,%2,%3}, [%4];" \
    : "=r"(R0),"=r"(R1),"=r"(R2),"=r"(R3) : "r"(ADDR))
#define MMA_BF16(D,A0,A1,A2,A3,B0,B1) \
  asm volatile("mma.sync.aligned.m16n8k16.row.col.f32.bf16.bf16.f32 " \
    "{%0,%1,%2,%3},{%4,%5,%6,%7},{%8,%9},{%0,%1,%2,%3};" \
    : "+f"(D[0]),"+f"(D[1]),"+f"(D[2]),"+f"(D[3]) \
    : "r"(A0),"r"(A1),"r"(A2),"r"(A3),"r"(B0),"r"(B1))

#define MBAR_INIT(ADDR, CNT) \
  asm volatile("mbarrier.init.shared.b64 [%0], %1;" :: "r"(ADDR), "r"(CNT) : "memory")
#define MBAR_EXPECT_TX(ADDR, BYTES) \
  asm volatile("mbarrier.arrive.expect_tx.shared.b64 _, [%0], %1;" :: "r"(ADDR), "r"(BYTES) : "memory")
#define BULK_LOAD(DST, SRC, BYTES, MBAR) \
  asm volatile("cp.async.bulk.shared::cluster.global.mbarrier::complete_tx::bytes [%0], [%1], %2, [%3];" \
    :: "r"(DST), "l"(SRC), "r"(BYTES), "r"(MBAR) : "memory")
#define MBAR_WAIT(ADDR, PAR) do { \
    asm volatile( \
        "{\n\t.reg .pred P;\n" \
        "WL%=:\n\t" \
        "mbarrier.try_wait.parity.acquire.cta.shared::cta.b64 P, [%0], %1, 0x989680;\n\t" \
        "@P bra WD%=;\n\t" \
        "bra WL%=;\n" \
        "WD%=:\n\t}" \
        :: "r"(ADDR), "r"(PAR) : "memory"); \
} while (0)

__device__ __forceinline__ uint32_t smem_u32(const void* p) {
    uint32_t a;
    asm("{ .reg .u64 t; cvta.to.shared.u64 t, %1; cvt.u32.u64 %0, t; }" : "=r"(a) : "l"(p));
    return a;
}

__device__ __forceinline__ void swish_derivs(float z, float& s, float& sp, float& spp) {
    float sig = 1.0f / (1.0f + __expf(-z));
    float om  = 1.0f - sig;
    s   = z * sig;
    sp  = sig * (1.0f + z * om);
    spp = sig * om * (2.0f + z * (1.0f - 2.0f * sig));
}

// write value as bf16 hi/lo into A buffers; row-major, 528B row stride
__device__ __forceinline__ void storeA(char* sm, int row, int k, float v) {
    const uint32_t o = (uint32_t)row * ASTR + (uint32_t)k * 2;
    __nv_bfloat16 hi = __float2bfloat16(v);
    float rem = v - __bfloat162float(hi);
    __nv_bfloat16 lo = __float2bfloat16(rem);
    *reinterpret_cast<__nv_bfloat16*>(sm + OFF_AHI + o) = hi;
    *reinterpret_cast<__nv_bfloat16*>(sm + OFF_ALO + o) = lo;
}

// ---- prep: split W1..W3 into bf16 hi/lo, stored in smem-image chunk layout ----
__global__ void prep_kernel(const float* __restrict__ W1, const float* __restrict__ W2,
                            const float* __restrict__ W3) {
    int i = blockIdx.x * blockDim.x + threadIdx.x;
    if (i >= 3 * 65536) return;
    const int layer = i >> 16;
    const int r = i & 65535;
    const int k = r >> 8;        // 0..255 (K index)
    const int n = r & 255;       // 0..255 (N index)
    const float* W = (layer == 0) ? W1 : (layer == 1) ? W2 : W3;
    const float w = W[r];
    __nv_bfloat16 hi = __float2bfloat16(w);
    float rem = w - __bfloat162float(hi);
    __nv_bfloat16 lo = __float2bfloat16(rem);
    const int chunk = k >> 4;
    const int kr = k & 15;
    const size_t base = (size_t)(layer * 16 + chunk) * BUF_BYTES + (size_t)kr * BSTR + (size_t)n * 2;
    *reinterpret_cast<__nv_bfloat16*>(g_Wstage + base) = hi;
    *reinterpret_cast<__nv_bfloat16*>(g_Wstage + base + BSPL) = lo;
}

// ---- main kernel ----
__global__ __launch_bounds__(TPB, 2)
void pinn_mma_kernel(
    const float* __restrict__ x, const float* __restrict__ y,
    const float* __restrict__ t, const float* __restrict__ nu,
    const float* __restrict__ W0, const float* __restrict__ b0,
    const float* __restrict__ b1, const float* __restrict__ b2,
    const float* __restrict__ b3,
    const float* __restrict__ W4, const float* __restrict__ b4,
    float* __restrict__ out, int N)
{
    extern __shared__ char smem_raw[];
    const uint32_t rawa = smem_u32(smem_raw);
    const uint32_t sbase = (rawa + 1023u) & ~1023u;
    char* sm = smem_raw + (sbase - rawa);
    float* scr = reinterpret_cast<float*>(sm + OFF_SCR);   // [48][260], aliases buffers

    const int tid  = threadIdx.x;
    const int wid  = tid >> 5;       // 0..7
    const int lane = tid & 31;
    const int base = blockIdx.x * NPTS;

    const int n0 = wid * 32;         // N group start (32 cols per warp)
    const int nn = tid;              // neuron for layer0/epilogue (0..255)

    const uint32_t mbar0 = sbase + OFF_MBAR;

    // init mbarriers
    if (tid == 0) {
        MBAR_INIT(mbar0 + 0,  1u);
        MBAR_INIT(mbar0 + 8,  1u);
        MBAR_INIT(mbar0 + 16, 1u);
    }
    __syncthreads();

    // issue fills for layer-0 chunks 0,1 behind the scalar layer-0 phase
    if (tid == 0) {
        MBAR_EXPECT_TX(mbar0 + 0, (uint32_t)BUF_BYTES);
        BULK_LOAD(sbase + OFF_B + 0 * BUF_BYTES, (const void*)(g_Wstage + 0 * BUF_BYTES),
                  (uint32_t)BUF_BYTES, mbar0 + 0);
        MBAR_EXPECT_TX(mbar0 + 8, (uint32_t)BUF_BYTES);
        BULK_LOAD(sbase + OFF_B + 1 * BUF_BYTES, (const void*)(g_Wstage + 1 * BUF_BYTES),
                  (uint32_t)BUF_BYTES, mbar0 + 8);
    }

    // ---------------- layer 0: (4 -> 256) scalar -> A hi/lo -----------------
    {
        const float w0 = W0[nn], w1 = W0[256 + nn], w2 = W0[512 + nn], w3 = W0[768 + nn];
        const float bb = b0[nn];
        #pragma unroll 1
        for (int p = 0; p < NPTS; p++) {
            int idx = base + p; if (idx >= N) idx = N - 1;
            const float xs = x[idx];
            const float ys = y[idx];
            const float ts = 2.0f * t[idx] - 1.0f;
            const float ns = 2.0f * (nu[idx] - 0.01f) * (1.0f / 0.09f) - 1.0f;
            const float z  = fmaf(xs, w0, fmaf(ys, w1, fmaf(ts, w2, fmaf(ns, w3, bb))));
            const float zx = w0, zy = w1, zt = 2.0f * w2;
            float s, sp, spp; swish_derivs(z, s, sp, spp);
            const int rb = p * 6;
            storeA(sm, rb + 0, nn, s);
            storeA(sm, rb + 1, nn, sp * zx);
            storeA(sm, rb + 2, nn, sp * zy);
            storeA(sm, rb + 3, nn, sp * zt);
            storeA(sm, rb + 4, nn, spp * zx * zx);
            storeA(sm, rb + 5, nn, spp * zy * zy);
        }
    }
    __syncthreads();

    // ---------------- 3 hidden layers: bf16-split GEMM + swish --------------
    #pragma unroll 1
    for (int L = 0; L < 3; L++) {
        const float* __restrict__ bptr = (L == 0) ? b1 : (L == 1) ? b2 : b3;

        float acc[3][4][4];   // [m-tile][n-tile(8 cols)][frag]
        #pragma unroll
        for (int m = 0; m < 3; m++)
            #pragma unroll
            for (int nt = 0; nt < 4; nt++)
                #pragma unroll
                for (int r = 0; r < 4; r++) acc[m][nt][r] = 0.0f;

        if (L > 0) {
            // issue fills for this layer's chunks 0,1 (buffers free: prior epilogue synced)
            const int g0 = L * 16;
            if (tid == 0) {
                #pragma unroll
                for (int j = 0; j < 2; j++) {
                    const int g = g0 + j;
                    const uint32_t mb = mbar0 + (uint32_t)(g % 3) * 8;
                    MBAR_EXPECT_TX(mb, (uint32_t)BUF_BYTES);
                    BULK_LOAD(sbase + OFF_B + (uint32_t)(g % 3) * BUF_BYTES,
                              (const void*)(g_Wstage + (size_t)g * BUF_BYTES),
                              (uint32_t)BUF_BYTES, mb);
                }
            }
        }

        #pragma unroll 1
        for (int c = 0; c < 16; c++) {
            const int g = L * 16 + c;
            __syncthreads();     // readers of chunk g-1 (buffer (g+2)%3) are done
            if (c + 2 < 16 && tid == 0) {
                const int g2 = g + 2;
                const uint32_t mb = mbar0 + (uint32_t)(g2 % 3) * 8;
                MBAR_EXPECT_TX(mb, (uint32_t)BUF_BYTES);
                BULK_LOAD(sbase + OFF_B + (uint32_t)(g2 % 3) * BUF_BYTES,
                          (const void*)(g_Wstage + (size_t)g2 * BUF_BYTES),
                          (uint32_t)BUF_BYTES, mb);
            }
            // wait for chunk g's fill
            MBAR_WAIT(mbar0 + (uint32_t)(g % 3) * 8, (uint32_t)((g / 3) & 1));

            const uint32_t bufb = sbase + OFF_B + (uint32_t)(g % 3) * BUF_BYTES;

            // load B fragments once: hi and lo
            uint32_t Bh[8], Bl[8];
            #pragma unroll
            for (int q = 0; q < 2; q++) {
                const uint32_t roff = (uint32_t)(lane & 15) * BSTR
                                    + (uint32_t)(n0 + q * 16 + (lane >> 4) * 8) * 2;
                LDSM4T(Bh[q * 4], Bh[q * 4 + 1], Bh[q * 4 + 2], Bh[q * 4 + 3], bufb + roff);
                LDSM4T(Bl[q * 4], Bl[q * 4 + 1], Bl[q * 4 + 2], Bl[q * 4 + 3], bufb + BSPL + roff);
            }
            // load ALL m-tiles' Ahi fragments up front
            uint32_t Ah[3][4];
            uint32_t aroff[3];
            #pragma unroll
            for (int m = 0; m < 3; m++) {
                aroff[m] = (uint32_t)(m * 16 + (lane & 15)) * ASTR
                         + (uint32_t)(c * 16 + (lane >> 4) * 8) * 2;
                LDSM4(Ah[m][0], Ah[m][1], Ah[m][2], Ah[m][3], sbase + OFF_AHI + aroff[m]);
            }
            // set 1: Ahi x Bhi
            #pragma unroll
            for (int m = 0; m < 3; m++)
                #pragma unroll
                for (int nt = 0; nt < 4; nt++)
                    MMA_BF16(acc[m][nt], Ah[m][0], Ah[m][1], Ah[m][2], Ah[m][3],
                             Bh[nt * 2], Bh[nt * 2 + 1]);
            // set 2: Ahi x Blo
            #pragma unroll
            for (int m = 0; m < 3; m++)
                #pragma unroll
                for (int nt = 0; nt < 4; nt++)
                    MMA_BF16(acc[m][nt], Ah[m][0], Ah[m][1], Ah[m][2], Ah[m][3],
                             Bl[nt * 2], Bl[nt * 2 + 1]);
            // load Alo, set 3: Alo x Bhi
            uint32_t Al[3][4];
            #pragma unroll
            for (int m = 0; m < 3; m++)
                LDSM4(Al[m][0], Al[m][1], Al[m][2], Al[m][3], sbase + OFF_ALO + aroff[m]);
            #pragma unroll
            for (int m = 0; m < 3; m++)
                #pragma unroll
                for (int nt = 0; nt < 4; nt++)
                    MMA_BF16(acc[m][nt], Al[m][0], Al[m][1], Al[m][2], Al[m][3],
                             Bh[nt * 2], Bh[nt * 2 + 1]);
        }
        __syncthreads();   // all MMA buffer reads done; scr (aliased) may now be written

        // ---- epilogue: accums -> scratch -> swish chain -> A hi/lo ----
        #pragma unroll
        for (int m = 0; m < 3; m++) {
            const int row = m * 16 + (lane >> 2);
            #pragma unroll
            for (int nt = 0; nt < 4; nt++) {
                const int col = n0 + nt * 8 + (lane & 3) * 2;
                float* p0 = scr + row * SCRSTR + col;
                p0[0] = acc[m][nt][0];
                p0[1] = acc[m][nt][1];
                float* p1 = p0 + 8 * SCRSTR;
                p1[0] = acc[m][nt][2];
                p1[1] = acc[m][nt][3];
            }
        }
        __syncthreads();

        {
            const float bn = bptr[nn];
            #pragma unroll 1
            for (int p = 0; p < NPTS; p++) {
                const float* zr = scr + (p * 6) * SCRSTR + nn;
                const float z   = zr[0] + bn;
                const float zx  = zr[1 * SCRSTR];
                const float zy  = zr[2 * SCRSTR];
                const float zt  = zr[3 * SCRSTR];
                const float zxx = zr[4 * SCRSTR];
                const float zyy = zr[5 * SCRSTR];
                float s, sp, spp; swish_derivs(z, s, sp, spp);
                const int rb = p * 6;
                storeA(sm, rb + 0, nn, s);
                storeA(sm, rb + 1, nn, sp * zx);
                storeA(sm, rb + 2, nn, sp * zy);
                storeA(sm, rb + 3, nn, sp * zt);
                storeA(sm, rb + 4, nn, fmaf(spp, zx * zx, sp * zxx));
                storeA(sm, rb + 5, nn, fmaf(spp, zy * zy, sp * zyy));
            }
        }
        __syncthreads();
    }

    // ---------------- final layer (256 -> 2) + residual ---------------------
    if (tid < MROWS) {
        const int row = tid;
        float au = 0.0f, av = 0.0f;
        #pragma unroll 1
        for (int i = 0; i < 32; i++) {
            const int k0 = i * 8;
            const uint32_t o = (uint32_t)row * ASTR + (uint32_t)k0 * 2;
            const uint4 vh = *reinterpret_cast<const uint4*>(sm + OFF_AHI + o);
            const uint4 vl = *reinterpret_cast<const uint4*>(sm + OFF_ALO + o);
            const __nv_bfloat16* ph2 = reinterpret_cast<const __nv_bfloat16*>(&vh);
            const __nv_bfloat16* pl2 = reinterpret_cast<const __nv_bfloat16*>(&vl);
            #pragma unroll
            for (int e = 0; e < 8; e++) {
                const float v = __bfloat162float(ph2[e]) + __bfloat162float(pl2[e]);
                const float2 w = *reinterpret_cast<const float2*>(&W4[2 * (k0 + e)]);
                au = fmaf(v, w.x, au);
                av = fmaf(v, w.y, av);
            }
        }
        scr[row * 2 + 0] = au;
        scr[row * 2 + 1] = av;
    }
    __syncthreads();

    if (tid < NPTS) {
        const int idx = base + tid;
        if (idx < N) {
            const int rb = tid * 6;
            const float u   = scr[(rb + 0) * 2 + 0] + b4[0];
            const float v   = scr[(rb + 0) * 2 + 1] + b4[1];
            const float u_x = scr[(rb + 1) * 2 + 0], v_x = scr[(rb + 1) * 2 + 1];
            const float u_y = scr[(rb + 2) * 2 + 0], v_y = scr[(rb + 2) * 2 + 1];
            const float u_t = scr[(rb + 3) * 2 + 0], v_t = scr[(rb + 3) * 2 + 1];
            const float uxx = scr[(rb + 4) * 2 + 0], vxx = scr[(rb + 4) * 2 + 1];
            const float uyy = scr[(rb + 5) * 2 + 0], vyy = scr[(rb + 5) * 2 + 1];
            const float nv = nu[idx];
            out[idx * 2 + 0] = u_t + u * u_x + v * u_y - nv * (uxx + uyy);
            out[idx * 2 + 1] = v_t + u * v_x + v * v_y - nv * (vxx + vyy);
        }
    }
}

extern "C" void kernel_launch(void* const* d_in, const int* in_sizes, int n_in,
                              void* d_out, int out_size) {
    const float* x  = (const float*)d_in[0];
    const float* y  = (const float*)d_in[1];
    const float* t  = (const float*)d_in[2];
    const float* nu = (const float*)d_in[3];
    const float* W0 = (const float*)d_in[4];
    const float* b0 = (const float*)d_in[5];
    const float* W1 = (const float*)d_in[6];
    const float* b1 = (const float*)d_in[7];
    const float* W2 = (const float*)d_in[8];
    const float* b2 = (const float*)d_in[9];
    const float* W3 = (const float*)d_in[10];
    const float* b3 = (const float*)d_in[11];
    const float* W4 = (const float*)d_in[12];
    const float* b4 = (const float*)d_in[13];
    float* out = (float*)d_out;

    const int N = in_sizes[0];

    cudaFuncSetAttribute(pinn_mma_kernel, cudaFuncAttributeMaxDynamicSharedMemorySize, SMEM_BYTES);

    prep_kernel<<<(3 * 65536 + 255) / 256, 256>>>(W1, W2, W3);

    const int blocks = (N + NPTS - 1) / NPTS;
    pinn_mma_kernel<<<blocks, TPB, SMEM_BYTES>>>(x, y, t, nu, W0, b0,
                                                 b1, b2, b3, W4, b4, out, N);
}

// round 13
// speedup vs baseline: 1.1731x; 1.0516x over previous
#include <cuda_runtime.h>
#include <cuda_bf16.h>
#include <cstdint>

#define NPTS 8            // points per CTA
#define MROWS 48          // 8 points x 6 channels
#define TPB 256           // 8 warps

// ---- SMEM layout (byte offsets from 1024-aligned base) ----
#define ASTR    528       // A row stride bytes (264 halves; 256 used + pad)
#define OFF_AHI 0         // 48*528 = 25344
#define OFF_ALO 25344     // ends 50688
#define OFF_B   50688     // 3 x chunk buffers of 16896 B (2 splits x 16 k-rows x 528 B)
#define BUF_BYTES 16896
#define BSPL    8448      // split offset inside a chunk buffer (16*528)
#define BSTR    528
#define OFF_SCR 50688     // fp32 scratch [48][260] = 49920 — ALIASES buffers (temporally disjoint)
#define SCRSTR  260
#define OFF_MBAR 101376   // 3 full + 3 empty mbarriers (48 B)
#define SMEM_BYTES (101376 + 64 + 1024)   // 102464 -> 2 CTAs/SM

// weights staged in EXACT smem-image layout: [layer][chunk16][split2][16 rows x 528B]
__device__ __align__(16) unsigned char g_Wstage[3 * 16 * BUF_BYTES];

#define LDSM4(R0,R1,R2,R3,ADDR) \
  asm volatile("ldmatrix.sync.aligned.m8n8.x4.shared.b16 {%0,%1,%2,%3}, [%4];" \
    : "=r"(R0),"=r"(R1),"=r"(R2),"=r"(R3) : "r"(ADDR))
#define LDSM4T(R0,R1,R2,R3,ADDR) \
  asm volatile("ldmatrix.sync.aligned.m8n8.x4.trans.shared.b16 {%0,%1,%2,%3}, [%4];" \
    : "=r"(R0),"=r"(R1),"=r"(R2),"=r"(R3) : "r"(ADDR))
#define MMA_BF16(D,A0,A1,A2,A3,B0,B1) \
  asm volatile("mma.sync.aligned.m16n8k16.row.col.f32.bf16.bf16.f32 " \
    "{%0,%1,%2,%3},{%4,%5,%6,%7},{%8,%9},{%0,%1,%2,%3};" \
    : "+f"(D[0]),"+f"(D[1]),"+f"(D[2]),"+f"(D[3]) \
    : "r"(A0),"r"(A1),"r"(A2),"r"(A3),"r"(B0),"r"(B1))

#define MBAR_INIT(ADDR, CNT) \
  asm volatile("mbarrier.init.shared.b64 [%0], %1;" :: "r"(ADDR), "r"(CNT) : "memory")
#define MBAR_EXPECT_TX(ADDR, BYTES) \
  asm volatile("mbarrier.arrive.expect_tx.shared.b64 _, [%0], %1;" :: "r"(ADDR), "r"(BYTES) : "memory")
#define MBAR_ARRIVE(ADDR) \
  asm volatile("mbarrier.arrive.shared.b64 _, [%0];" :: "r"(ADDR) : "memory")
#define BULK_LOAD(DST, SRC, BYTES, MBAR) \
  asm volatile("cp.async.bulk.shared::cluster.global.mbarrier::complete_tx::bytes [%0], [%1], %2, [%3];" \
    :: "r"(DST), "l"(SRC), "r"(BYTES), "r"(MBAR) : "memory")
#define MBAR_WAIT(ADDR, PAR) do { \
    asm volatile( \
        "{\n\t.reg .pred P;\n" \
        "WL%=:\n\t" \
        "mbarrier.try_wait.parity.acquire.cta.shared::cta.b64 P, [%0], %1, 0x989680;\n\t" \
        "@P bra WD%=;\n\t" \
        "bra WL%=;\n" \
        "WD%=:\n\t}" \
        :: "r"(ADDR), "r"(PAR) : "memory"); \
} while (0)

__device__ __forceinline__ uint32_t smem_u32(const void* p) {
    uint32_t a;
    asm("{ .reg .u64 t; cvta.to.shared.u64 t, %1; cvt.u32.u64 %0, t; }" : "=r"(a) : "l"(p));
    return a;
}

__device__ __forceinline__ void swish_derivs(float z, float& s, float& sp, float& spp) {
    float sig = 1.0f / (1.0f + __expf(-z));
    float om  = 1.0f - sig;
    s   = z * sig;
    sp  = sig * (1.0f + z * om);
    spp = sig * om * (2.0f + z * (1.0f - 2.0f * sig));
}

// write value as bf16 hi/lo into A buffers; row-major, 528B row stride
__device__ __forceinline__ void storeA(char* sm, int row, int k, float v) {
    const uint32_t o = (uint32_t)row * ASTR + (uint32_t)k * 2;
    __nv_bfloat16 hi = __float2bfloat16(v);
    float rem = v - __bfloat162float(hi);
    __nv_bfloat16 lo = __float2bfloat16(rem);
    *reinterpret_cast<__nv_bfloat16*>(sm + OFF_AHI + o) = hi;
    *reinterpret_cast<__nv_bfloat16*>(sm + OFF_ALO + o) = lo;
}

// ---- prep: split W1..W3 into bf16 hi/lo, stored in smem-image chunk layout ----
__global__ void prep_kernel(const float* __restrict__ W1, const float* __restrict__ W2,
                            const float* __restrict__ W3) {
    int i = blockIdx.x * blockDim.x + threadIdx.x;
    if (i >= 3 * 65536) return;
    const int layer = i >> 16;
    const int r = i & 65535;
    const int k = r >> 8;        // 0..255 (K index)
    const int n = r & 255;       // 0..255 (N index)
    const float* W = (layer == 0) ? W1 : (layer == 1) ? W2 : W3;
    const float w = W[r];
    __nv_bfloat16 hi = __float2bfloat16(w);
    float rem = w - __bfloat162float(hi);
    __nv_bfloat16 lo = __float2bfloat16(rem);
    const int chunk = k >> 4;
    const int kr = k & 15;
    const size_t base = (size_t)(layer * 16 + chunk) * BUF_BYTES + (size_t)kr * BSTR + (size_t)n * 2;
    *reinterpret_cast<__nv_bfloat16*>(g_Wstage + base) = hi;
    *reinterpret_cast<__nv_bfloat16*>(g_Wstage + base + BSPL) = lo;
}

// producer: fill global-chunk g into buffer g%3 (waits buffer-empty for rounds >= 1)
__device__ __forceinline__ void issue_fill(uint32_t sbase, int g) {
    const uint32_t mbf = sbase + OFF_MBAR + (uint32_t)(g % 3) * 8;        // full
    const uint32_t mbe = sbase + OFF_MBAR + 24 + (uint32_t)(g % 3) * 8;   // empty
    const int r = g / 3;
    if (r >= 1) MBAR_WAIT(mbe, (uint32_t)((r - 1) & 1));
    MBAR_EXPECT_TX(mbf, (uint32_t)BUF_BYTES);
    BULK_LOAD(sbase + OFF_B + (uint32_t)(g % 3) * BUF_BYTES,
              (const void*)(g_Wstage + (size_t)g * BUF_BYTES),
              (uint32_t)BUF_BYTES, mbf);
}

// ---- main kernel ----
__global__ __launch_bounds__(TPB, 2)
void pinn_mma_kernel(
    const float* __restrict__ x, const float* __restrict__ y,
    const float* __restrict__ t, const float* __restrict__ nu,
    const float* __restrict__ W0, const float* __restrict__ b0,
    const float* __restrict__ b1, const float* __restrict__ b2,
    const float* __restrict__ b3,
    const float* __restrict__ W4, const float* __restrict__ b4,
    float* __restrict__ out, int N)
{
    extern __shared__ char smem_raw[];
    const uint32_t rawa = smem_u32(smem_raw);
    const uint32_t sbase = (rawa + 1023u) & ~1023u;
    char* sm = smem_raw + (sbase - rawa);
    float* scr = reinterpret_cast<float*>(sm + OFF_SCR);   // [48][260], aliases buffers

    const int tid  = threadIdx.x;
    const int wid  = tid >> 5;       // 0..7
    const int lane = tid & 31;
    const int base = blockIdx.x * NPTS;

    const int n0 = wid * 32;         // N group start (32 cols per warp)
    const int nn = tid;              // neuron for layer0/epilogue (0..255)

    const uint32_t mbarF = sbase + OFF_MBAR;        // 3 full barriers
    const uint32_t mbarE = sbase + OFF_MBAR + 24;   // 3 empty barriers

    // init mbarriers
    if (tid == 0) {
        #pragma unroll
        for (int i = 0; i < 3; i++) {
            MBAR_INIT(mbarF + (uint32_t)i * 8, 1u);
            MBAR_INIT(mbarE + (uint32_t)i * 8, 8u);   // one arrival per warp
        }
    }
    __syncthreads();

    // fills for layer-0 chunks 0,1 behind the scalar layer-0 phase (round 0: no empty wait)
    if (tid == 0) { issue_fill(sbase, 0); issue_fill(sbase, 1); }

    // ---------------- layer 0: (4 -> 256) scalar -> A hi/lo -----------------
    {
        const float w0 = W0[nn], w1 = W0[256 + nn], w2 = W0[512 + nn], w3 = W0[768 + nn];
        const float bb = b0[nn];
        #pragma unroll 1
        for (int p = 0; p < NPTS; p++) {
            int idx = base + p; if (idx >= N) idx = N - 1;
            const float xs = x[idx];
            const float ys = y[idx];
            const float ts = 2.0f * t[idx] - 1.0f;
            const float ns = 2.0f * (nu[idx] - 0.01f) * (1.0f / 0.09f) - 1.0f;
            const float z  = fmaf(xs, w0, fmaf(ys, w1, fmaf(ts, w2, fmaf(ns, w3, bb))));
            const float zx = w0, zy = w1, zt = 2.0f * w2;
            float s, sp, spp; swish_derivs(z, s, sp, spp);
            const int rb = p * 6;
            storeA(sm, rb + 0, nn, s);
            storeA(sm, rb + 1, nn, sp * zx);
            storeA(sm, rb + 2, nn, sp * zy);
            storeA(sm, rb + 3, nn, sp * zt);
            storeA(sm, rb + 4, nn, spp * zx * zx);
            storeA(sm, rb + 5, nn, spp * zy * zy);
        }
    }
    __syncthreads();

    // ---------------- 3 hidden layers: bf16-split GEMM + swish --------------
    #pragma unroll 1
    for (int L = 0; L < 3; L++) {
        const float* __restrict__ bptr = (L == 0) ? b1 : (L == 1) ? b2 : b3;

        float acc[3][4][4];   // [m-tile][n-tile(8 cols)][frag]
        #pragma unroll
        for (int m = 0; m < 3; m++)
            #pragma unroll
            for (int nt = 0; nt < 4; nt++)
                #pragma unroll
                for (int r = 0; r < 4; r++) acc[m][nt][r] = 0.0f;

        // mainloop: NO block-wide syncs; warps self-schedule on the mbarrier ring
        #pragma unroll 1
        for (int c = 0; c < 16; c++) {
            const int g = L * 16 + c;
            if (tid == 0 && c + 2 < 16) issue_fill(sbase, g + 2);

            // wait chunk g's fill
            MBAR_WAIT(mbarF + (uint32_t)(g % 3) * 8, (uint32_t)((g / 3) & 1));

            const uint32_t bufb = sbase + OFF_B + (uint32_t)(g % 3) * BUF_BYTES;

            // load B fragments once: hi and lo (only buffer reads)
            uint32_t Bh[8], Bl[8];
            #pragma unroll
            for (int q = 0; q < 2; q++) {
                const uint32_t roff = (uint32_t)(lane & 15) * BSTR
                                    + (uint32_t)(n0 + q * 16 + (lane >> 4) * 8) * 2;
                LDSM4T(Bh[q * 4], Bh[q * 4 + 1], Bh[q * 4 + 2], Bh[q * 4 + 3], bufb + roff);
                LDSM4T(Bl[q * 4], Bl[q * 4 + 1], Bl[q * 4 + 2], Bl[q * 4 + 3], bufb + BSPL + roff);
            }
            // buffer reads complete -> this warp frees the buffer
            // (defer last 3 chunks' arrivals until after epilogue: scr aliases buffers)
            if (lane == 0 && c < 13) MBAR_ARRIVE(mbarE + (uint32_t)(g % 3) * 8);

            // load ALL m-tiles' Ahi fragments up front (A region, not buffers)
            uint32_t Ah[3][4];
            uint32_t aroff[3];
            #pragma unroll
            for (int m = 0; m < 3; m++) {
                aroff[m] = (uint32_t)(m * 16 + (lane & 15)) * ASTR
                         + (uint32_t)(c * 16 + (lane >> 4) * 8) * 2;
                LDSM4(Ah[m][0], Ah[m][1], Ah[m][2], Ah[m][3], sbase + OFF_AHI + aroff[m]);
            }
            // set 1: Ahi x Bhi
            #pragma unroll
            for (int m = 0; m < 3; m++)
                #pragma unroll
                for (int nt = 0; nt < 4; nt++)
                    MMA_BF16(acc[m][nt], Ah[m][0], Ah[m][1], Ah[m][2], Ah[m][3],
                             Bh[nt * 2], Bh[nt * 2 + 1]);
            // set 2: Ahi x Blo
            #pragma unroll
            for (int m = 0; m < 3; m++)
                #pragma unroll
                for (int nt = 0; nt < 4; nt++)
                    MMA_BF16(acc[m][nt], Ah[m][0], Ah[m][1], Ah[m][2], Ah[m][3],
                             Bl[nt * 2], Bl[nt * 2 + 1]);
            // load Alo, set 3: Alo x Bhi
            uint32_t Al[3][4];
            #pragma unroll
            for (int m = 0; m < 3; m++)
                LDSM4(Al[m][0], Al[m][1], Al[m][2], Al[m][3], sbase + OFF_ALO + aroff[m]);
            #pragma unroll
            for (int m = 0; m < 3; m++)
                #pragma unroll
                for (int nt = 0; nt < 4; nt++)
                    MMA_BF16(acc[m][nt], Al[m][0], Al[m][1], Al[m][2], Al[m][3],
                             Bh[nt * 2], Bh[nt * 2 + 1]);
        }
        __syncthreads();   // ALL warps done with buffers; scr (aliased) may now be written

        // ---- epilogue: accums -> scratch -> swish chain -> A hi/lo ----
        #pragma unroll
        for (int m = 0; m < 3; m++) {
            const int row = m * 16 + (lane >> 2);
            #pragma unroll
            for (int nt = 0; nt < 4; nt++) {
                const int col = n0 + nt * 8 + (lane & 3) * 2;
                float* p0 = scr + row * SCRSTR + col;
                p0[0] = acc[m][nt][0];
                p0[1] = acc[m][nt][1];
                float* p1 = p0 + 8 * SCRSTR;
                p1[0] = acc[m][nt][2];
                p1[1] = acc[m][nt][3];
            }
        }
        __syncthreads();

        {
            const float bn = bptr[nn];
            #pragma unroll 1
            for (int p = 0; p < NPTS; p++) {
                const float* zr = scr + (p * 6) * SCRSTR + nn;
                const float z   = zr[0] + bn;
                const float zx  = zr[1 * SCRSTR];
                const float zy  = zr[2 * SCRSTR];
                const float zt  = zr[3 * SCRSTR];
                const float zxx = zr[4 * SCRSTR];
                const float zyy = zr[5 * SCRSTR];
                float s, sp, spp; swish_derivs(z, s, sp, spp);
                const int rb = p * 6;
                storeA(sm, rb + 0, nn, s);
                storeA(sm, rb + 1, nn, sp * zx);
                storeA(sm, rb + 2, nn, sp * zy);
                storeA(sm, rb + 3, nn, sp * zt);
                storeA(sm, rb + 4, nn, fmaf(spp, zx * zx, sp * zxx));
                storeA(sm, rb + 5, nn, fmaf(spp, zy * zy, sp * zyy));
            }
        }
        // scr reads done for this warp -> release deferred buffers (chunks 13,14,15)
        if (L < 2 && lane == 0) {
            #pragma unroll
            for (int j = 13; j < 16; j++)
                MBAR_ARRIVE(mbarE + (uint32_t)((L * 16 + j) % 3) * 8);
        }
        __syncthreads();   // A visible to all warps before next layer's LDSM

        // issue next layer's first two fills (empties just released)
        if (L < 2 && tid == 0) {
            issue_fill(sbase, (L + 1) * 16);
            issue_fill(sbase, (L + 1) * 16 + 1);
        }
    }

    // ---------------- final layer (256 -> 2) + residual ---------------------
    if (tid < MROWS) {
        const int row = tid;
        float au = 0.0f, av = 0.0f;
        #pragma unroll 1
        for (int i = 0; i < 32; i++) {
            const int k0 = i * 8;
            const uint32_t o = (uint32_t)row * ASTR + (uint32_t)k0 * 2;
            const uint4 vh = *reinterpret_cast<const uint4*>(sm + OFF_AHI + o);
            const uint4 vl = *reinterpret_cast<const uint4*>(sm + OFF_ALO + o);
            const __nv_bfloat16* ph2 = reinterpret_cast<const __nv_bfloat16*>(&vh);
            const __nv_bfloat16* pl2 = reinterpret_cast<const __nv_bfloat16*>(&vl);
            #pragma unroll
            for (int e = 0; e < 8; e++) {
                const float v = __bfloat162float(ph2[e]) + __bfloat162float(pl2[e]);
                const float2 w = *reinterpret_cast<const float2*>(&W4[2 * (k0 + e)]);
                au = fmaf(v, w.x, au);
                av = fmaf(v, w.y, av);
            }
        }
        scr[row * 2 + 0] = au;
        scr[row * 2 + 1] = av;
    }
    __syncthreads();

    if (tid < NPTS) {
        const int idx = base + tid;
        if (idx < N) {
            const int rb = tid * 6;
            const float u   = scr[(rb + 0) * 2 + 0] + b4[0];
            const float v   = scr[(rb + 0) * 2 + 1] + b4[1];
            const float u_x = scr[(rb + 1) * 2 + 0], v_x = scr[(rb + 1) * 2 + 1];
            const float u_y = scr[(rb + 2) * 2 + 0], v_y = scr[(rb + 2) * 2 + 1];
            const float u_t = scr[(rb + 3) * 2 + 0], v_t = scr[(rb + 3) * 2 + 1];
            const float uxx = scr[(rb + 4) * 2 + 0], vxx = scr[(rb + 4) * 2 + 1];
            const float uyy = scr[(rb + 5) * 2 + 0], vyy = scr[(rb + 5) * 2 + 1];
            const float nv = nu[idx];
            out[idx * 2 + 0] = u_t + u * u_x + v * u_y - nv * (uxx + uyy);
            out[idx * 2 + 1] = v_t + u * v_x + v * v_y - nv * (vxx + vyy);
        }
    }
}

extern "C" void kernel_launch(void* const* d_in, const int* in_sizes, int n_in,
                              void* d_out, int out_size) {
    const float* x  = (const float*)d_in[0];
    const float* y  = (const float*)d_in[1];
    const float* t  = (const float*)d_in[2];
    const float* nu = (const float*)d_in[3];
    const float* W0 = (const float*)d_in[4];
    const float* b0 = (const float*)d_in[5];
    const float* W1 = (const float*)d_in[6];
    const float* b1 = (const float*)d_in[7];
    const float* W2 = (const float*)d_in[8];
    const float* b2 = (const float*)d_in[9];
    const float* W3 = (const float*)d_in[10];
    const float* b3 = (const float*)d_in[11];
    const float* W4 = (const float*)d_in[12];
    const float* b4 = (const float*)d_in[13];
    float* out = (float*)d_out;

    const int N = in_sizes[0];

    cudaFuncSetAttribute(pinn_mma_kernel, cudaFuncAttributeMaxDynamicSharedMemorySize, SMEM_BYTES);

    prep_kernel<<<(3 * 65536 + 255) / 256, 256>>>(W1, W2, W3);

    const int blocks = (N + NPTS - 1) / NPTS;
    pinn_mma_kernel<<<blocks, TPB, SMEM_BYTES>>>(x, y, t, nu, W0, b0,
                                                 b1, b2, b3, W4, b4, out, N);
}

// round 14
// speedup vs baseline: 1.2198x; 1.0398x over previous
#include <cuda_runtime.h>
#include <cuda_bf16.h>
#include <cstdint>

#define NPTS 8            // points per CTA
#define MROWS 48          // 8 points x 6 channels
#define TPB 256           // 8 warps

// ---- SMEM layout (byte offsets from 1024-aligned base) ----
// A is stored TRANSPOSED: A'[k][m], 256 k-rows x 48 m-cols (+pad), 112B row stride
#define ASTR_T  112
#define OFF_AHI 0         // 256*112 = 28672
#define OFF_ALO 28672     // ends 57344
#define OFF_B   57344     // 3 x chunk buffers of 16896 B (2 splits x 16 k-rows x 528 B)
#define BUF_BYTES 16896
#define BSPL    8448
#define BSTR    528
#define OFF_SCR 57344     // fp32 scratch [48][260] = 49920 — ALIASES buffers
#define SCRSTR  260
#define OFF_MBAR 108032   // 3 full + 3 empty mbarriers
#define SMEM_BYTES (108032 + 64 + 1024)   // 109120 -> 2 CTAs/SM

// weights staged in EXACT smem-image layout: [layer][chunk16][split2][16 rows x 528B]
__device__ __align__(16) unsigned char g_Wstage[3 * 16 * BUF_BYTES];

#define LDSM4T(R0,R1,R2,R3,ADDR) \
  asm volatile("ldmatrix.sync.aligned.m8n8.x4.trans.shared.b16 {%0,%1,%2,%3}, [%4];" \
    : "=r"(R0),"=r"(R1),"=r"(R2),"=r"(R3) : "r"(ADDR))
#define MMA_BF16(D,A0,A1,A2,A3,B0,B1) \
  asm volatile("mma.sync.aligned.m16n8k16.row.col.f32.bf16.bf16.f32 " \
    "{%0,%1,%2,%3},{%4,%5,%6,%7},{%8,%9},{%0,%1,%2,%3};" \
    : "+f"(D[0]),"+f"(D[1]),"+f"(D[2]),"+f"(D[3]) \
    : "r"(A0),"r"(A1),"r"(A2),"r"(A3),"r"(B0),"r"(B1))

#define MBAR_INIT(ADDR, CNT) \
  asm volatile("mbarrier.init.shared.b64 [%0], %1;" :: "r"(ADDR), "r"(CNT) : "memory")
#define MBAR_EXPECT_TX(ADDR, BYTES) \
  asm volatile("mbarrier.arrive.expect_tx.shared.b64 _, [%0], %1;" :: "r"(ADDR), "r"(BYTES) : "memory")
#define MBAR_ARRIVE(ADDR) \
  asm volatile("mbarrier.arrive.shared.b64 _, [%0];" :: "r"(ADDR) : "memory")
#define BULK_LOAD(DST, SRC, BYTES, MBAR) \
  asm volatile("cp.async.bulk.shared::cluster.global.mbarrier::complete_tx::bytes [%0], [%1], %2, [%3];" \
    :: "r"(DST), "l"(SRC), "r"(BYTES), "r"(MBAR) : "memory")
#define MBAR_WAIT(ADDR, PAR) do { \
    asm volatile( \
        "{\n\t.reg .pred P;\n" \
        "WL%=:\n\t" \
        "mbarrier.try_wait.parity.acquire.cta.shared::cta.b64 P, [%0], %1, 0x989680;\n\t" \
        "@P bra WD%=;\n\t" \
        "bra WL%=;\n" \
        "WD%=:\n\t}" \
        :: "r"(ADDR), "r"(PAR) : "memory"); \
} while (0)

__device__ __forceinline__ uint32_t smem_u32(const void* p) {
    uint32_t a;
    asm("{ .reg .u64 t; cvta.to.shared.u64 t, %1; cvt.u32.u64 %0, t; }" : "=r"(a) : "l"(p));
    return a;
}

__device__ __forceinline__ void swish_derivs(float z, float& s, float& sp, float& spp) {
    float sig = 1.0f / (1.0f + __expf(-z));
    float om  = 1.0f - sig;
    s   = z * sig;
    sp  = sig * (1.0f + z * om);
    spp = sig * om * (2.0f + z * (1.0f - 2.0f * sig));
}

// split a,b into bf16 hi/lo and pack pairwise into bf16x2 words
__device__ __forceinline__ void split_pack(float a, float b, uint32_t& hp, uint32_t& lp) {
    __nv_bfloat16 ha = __float2bfloat16(a);
    __nv_bfloat16 hb = __float2bfloat16(b);
    __nv_bfloat16 la = __float2bfloat16(a - __bfloat162float(ha));
    __nv_bfloat16 lb = __float2bfloat16(b - __bfloat162float(hb));
    uint16_t uha = *reinterpret_cast<uint16_t*>(&ha);
    uint16_t uhb = *reinterpret_cast<uint16_t*>(&hb);
    uint16_t ula = *reinterpret_cast<uint16_t*>(&la);
    uint16_t ulb = *reinterpret_cast<uint16_t*>(&lb);
    hp = (uint32_t)uha | ((uint32_t)uhb << 16);
    lp = (uint32_t)ula | ((uint32_t)ulb << 16);
}

// ---- prep: split W1..W3 into bf16 hi/lo, stored in smem-image chunk layout ----
__global__ void prep_kernel(const float* __restrict__ W1, const float* __restrict__ W2,
                            const float* __restrict__ W3) {
    int i = blockIdx.x * blockDim.x + threadIdx.x;
    if (i >= 3 * 65536) return;
    const int layer = i >> 16;
    const int r = i & 65535;
    const int k = r >> 8;
    const int n = r & 255;
    const float* W = (layer == 0) ? W1 : (layer == 1) ? W2 : W3;
    const float w = W[r];
    __nv_bfloat16 hi = __float2bfloat16(w);
    float rem = w - __bfloat162float(hi);
    __nv_bfloat16 lo = __float2bfloat16(rem);
    const int chunk = k >> 4;
    const int kr = k & 15;
    const size_t base = (size_t)(layer * 16 + chunk) * BUF_BYTES + (size_t)kr * BSTR + (size_t)n * 2;
    *reinterpret_cast<__nv_bfloat16*>(g_Wstage + base) = hi;
    *reinterpret_cast<__nv_bfloat16*>(g_Wstage + base + BSPL) = lo;
}

// producer: fill global-chunk g into buffer g%3 (waits buffer-empty for rounds >= 1)
__device__ __forceinline__ void issue_fill(uint32_t sbase, int g) {
    const uint32_t mbf = sbase + OFF_MBAR + (uint32_t)(g % 3) * 8;
    const uint32_t mbe = sbase + OFF_MBAR + 24 + (uint32_t)(g % 3) * 8;
    const int r = g / 3;
    if (r >= 1) MBAR_WAIT(mbe, (uint32_t)((r - 1) & 1));
    MBAR_EXPECT_TX(mbf, (uint32_t)BUF_BYTES);
    BULK_LOAD(sbase + OFF_B + (uint32_t)(g % 3) * BUF_BYTES,
              (const void*)(g_Wstage + (size_t)g * BUF_BYTES),
              (uint32_t)BUF_BYTES, mbf);
}

// ---- main kernel ----
__global__ __launch_bounds__(TPB, 2)
void pinn_mma_kernel(
    const float* __restrict__ x, const float* __restrict__ y,
    const float* __restrict__ t, const float* __restrict__ nu,
    const float* __restrict__ W0, const float* __restrict__ b0,
    const float* __restrict__ b1, const float* __restrict__ b2,
    const float* __restrict__ b3,
    const float* __restrict__ W4, const float* __restrict__ b4,
    float* __restrict__ out, int N)
{
    extern __shared__ char smem_raw[];
    const uint32_t rawa = smem_u32(smem_raw);
    const uint32_t sbase = (rawa + 1023u) & ~1023u;
    char* sm = smem_raw + (sbase - rawa);
    float* scr = reinterpret_cast<float*>(sm + OFF_SCR);   // [48][260], aliases buffers

    const int tid  = threadIdx.x;
    const int wid  = tid >> 5;
    const int lane = tid & 31;
    const int base = blockIdx.x * NPTS;

    const int n0 = wid * 32;         // N group start (32 cols per warp)
    const int nn = tid;              // neuron (0..255)

    const uint32_t mbarF = sbase + OFF_MBAR;
    const uint32_t mbarE = sbase + OFF_MBAR + 24;

    if (tid == 0) {
        #pragma unroll
        for (int i = 0; i < 3; i++) {
            MBAR_INIT(mbarF + (uint32_t)i * 8, 1u);
            MBAR_INIT(mbarE + (uint32_t)i * 8, 8u);
        }
    }
    __syncthreads();

    if (tid == 0) { issue_fill(sbase, 0); issue_fill(sbase, 1); }

    // ---------------- layer 0: (4 -> 256) scalar -> A' row nn ----------------
    {
        const float w0 = W0[nn], w1 = W0[256 + nn], w2 = W0[512 + nn], w3 = W0[768 + nn];
        const float bb = b0[nn];
        uint32_t h32[24], l32[24];
        #pragma unroll
        for (int p = 0; p < NPTS; p++) {
            int idx = base + p; if (idx >= N) idx = N - 1;
            const float xs = x[idx];
            const float ys = y[idx];
            const float ts = 2.0f * t[idx] - 1.0f;
            const float ns = 2.0f * (nu[idx] - 0.01f) * (1.0f / 0.09f) - 1.0f;
            const float z  = fmaf(xs, w0, fmaf(ys, w1, fmaf(ts, w2, fmaf(ns, w3, bb))));
            const float zx = w0, zy = w1, zt = 2.0f * w2;
            float s, sp, spp; swish_derivs(z, s, sp, spp);
            split_pack(s,            sp * zx,      h32[p * 3 + 0], l32[p * 3 + 0]);
            split_pack(sp * zy,      sp * zt,      h32[p * 3 + 1], l32[p * 3 + 1]);
            split_pack(spp * zx * zx, spp * zy * zy, h32[p * 3 + 2], l32[p * 3 + 2]);
        }
        uint4* dh = reinterpret_cast<uint4*>(sm + OFF_AHI + nn * ASTR_T);
        uint4* dl = reinterpret_cast<uint4*>(sm + OFF_ALO + nn * ASTR_T);
        #pragma unroll
        for (int j = 0; j < 6; j++) {
            dh[j] = make_uint4(h32[4*j], h32[4*j+1], h32[4*j+2], h32[4*j+3]);
            dl[j] = make_uint4(l32[4*j], l32[4*j+1], l32[4*j+2], l32[4*j+3]);
        }
    }
    __syncthreads();

    // ---------------- 3 hidden layers: bf16-split GEMM + swish --------------
    #pragma unroll 1
    for (int L = 0; L < 3; L++) {
        const float* __restrict__ bptr = (L == 0) ? b1 : (L == 1) ? b2 : b3;

        float acc[3][4][4];
        #pragma unroll
        for (int m = 0; m < 3; m++)
            #pragma unroll
            for (int nt = 0; nt < 4; nt++)
                #pragma unroll
                for (int r = 0; r < 4; r++) acc[m][nt][r] = 0.0f;

        #pragma unroll 1
        for (int c = 0; c < 16; c++) {
            const int g = L * 16 + c;
            if (tid == 0 && c + 2 < 16) issue_fill(sbase, g + 2);

            MBAR_WAIT(mbarF + (uint32_t)(g % 3) * 8, (uint32_t)((g / 3) & 1));

            const uint32_t bufb = sbase + OFF_B + (uint32_t)(g % 3) * BUF_BYTES;

            uint32_t Bh[8], Bl[8];
            #pragma unroll
            for (int q = 0; q < 2; q++) {
                const uint32_t roff = (uint32_t)(lane & 15) * BSTR
                                    + (uint32_t)(n0 + q * 16 + (lane >> 4) * 8) * 2;
                LDSM4T(Bh[q * 4], Bh[q * 4 + 1], Bh[q * 4 + 2], Bh[q * 4 + 3], bufb + roff);
                LDSM4T(Bl[q * 4], Bl[q * 4 + 1], Bl[q * 4 + 2], Bl[q * 4 + 3], bufb + BSPL + roff);
            }
            if (lane == 0 && c < 13) MBAR_ARRIVE(mbarE + (uint32_t)(g % 3) * 8);

            // A fragments from transposed A' via trans ldmatrix
            // rows (k) : c*16 + (lane&7) + (lane>>4)*8 ; col (m) : m*16 + ((lane>>3)&1)*8
            uint32_t Ah[3][4];
            uint32_t aroff[3];
            const uint32_t krow = (uint32_t)(c * 16 + (lane & 7) + ((lane >> 4) << 3));
            const uint32_t mcol = (uint32_t)(((lane >> 3) & 1) * 8) * 2;
            #pragma unroll
            for (int m = 0; m < 3; m++) {
                aroff[m] = krow * ASTR_T + (uint32_t)(m * 16) * 2 + mcol;
                LDSM4T(Ah[m][0], Ah[m][1], Ah[m][2], Ah[m][3], sbase + OFF_AHI + aroff[m]);
            }
            #pragma unroll
            for (int m = 0; m < 3; m++)
                #pragma unroll
                for (int nt = 0; nt < 4; nt++)
                    MMA_BF16(acc[m][nt], Ah[m][0], Ah[m][1], Ah[m][2], Ah[m][3],
                             Bh[nt * 2], Bh[nt * 2 + 1]);
            #pragma unroll
            for (int m = 0; m < 3; m++)
                #pragma unroll
                for (int nt = 0; nt < 4; nt++)
                    MMA_BF16(acc[m][nt], Ah[m][0], Ah[m][1], Ah[m][2], Ah[m][3],
                             Bl[nt * 2], Bl[nt * 2 + 1]);
            uint32_t Al[3][4];
            #pragma unroll
            for (int m = 0; m < 3; m++)
                LDSM4T(Al[m][0], Al[m][1], Al[m][2], Al[m][3], sbase + OFF_ALO + aroff[m]);
            #pragma unroll
            for (int m = 0; m < 3; m++)
                #pragma unroll
                for (int nt = 0; nt < 4; nt++)
                    MMA_BF16(acc[m][nt], Al[m][0], Al[m][1], Al[m][2], Al[m][3],
                             Bh[nt * 2], Bh[nt * 2 + 1]);
        }
        __syncthreads();   // all buffer reads done; scr (aliased) may now be written

        // ---- epilogue: accums -> scratch ----
        #pragma unroll
        for (int m = 0; m < 3; m++) {
            const int row = m * 16 + (lane >> 2);
            #pragma unroll
            for (int nt = 0; nt < 4; nt++) {
                const int col = n0 + nt * 8 + (lane & 3) * 2;
                float* p0 = scr + row * SCRSTR + col;
                p0[0] = acc[m][nt][0];
                p0[1] = acc[m][nt][1];
                float* p1 = p0 + 8 * SCRSTR;
                p1[0] = acc[m][nt][2];
                p1[1] = acc[m][nt][3];
            }
        }
        __syncthreads();

        if (L < 2) {
            // swish chain -> A' row nn (vectorized)
            const float bn = bptr[nn];
            uint32_t h32[24], l32[24];
            #pragma unroll
            for (int p = 0; p < NPTS; p++) {
                const float* zr = scr + (p * 6) * SCRSTR + nn;
                const float z   = zr[0] + bn;
                const float zx  = zr[1 * SCRSTR];
                const float zy  = zr[2 * SCRSTR];
                const float zt  = zr[3 * SCRSTR];
                const float zxx = zr[4 * SCRSTR];
                const float zyy = zr[5 * SCRSTR];
                float s, sp, spp; swish_derivs(z, s, sp, spp);
                split_pack(s,       sp * zx, h32[p * 3 + 0], l32[p * 3 + 0]);
                split_pack(sp * zy, sp * zt, h32[p * 3 + 1], l32[p * 3 + 1]);
                split_pack(fmaf(spp, zx * zx, sp * zxx),
                           fmaf(spp, zy * zy, sp * zyy), h32[p * 3 + 2], l32[p * 3 + 2]);
            }
            uint4* dh = reinterpret_cast<uint4*>(sm + OFF_AHI + nn * ASTR_T);
            uint4* dl = reinterpret_cast<uint4*>(sm + OFF_ALO + nn * ASTR_T);
            #pragma unroll
            for (int j = 0; j < 6; j++) {
                dh[j] = make_uint4(h32[4*j], h32[4*j+1], h32[4*j+2], h32[4*j+3]);
                dl[j] = make_uint4(l32[4*j], l32[4*j+1], l32[4*j+2], l32[4*j+3]);
            }
            // release deferred buffers (chunks 13,14,15) after scr reads
            if (lane == 0) {
                #pragma unroll
                for (int j = 13; j < 16; j++)
                    MBAR_ARRIVE(mbarE + (uint32_t)((L * 16 + j) % 3) * 8);
            }
            __syncthreads();   // A' visible before next layer's LDSM
            if (tid == 0) {
                issue_fill(sbase, (L + 1) * 16);
                issue_fill(sbase, (L + 1) * 16 + 1);
            }
        } else {
            // last layer: write fp32 swish-chain results IN-PLACE to scr
            const float bn = bptr[nn];
            #pragma unroll
            for (int p = 0; p < NPTS; p++) {
                float* zr = scr + (p * 6) * SCRSTR + nn;
                const float z   = zr[0] + bn;
                const float zx  = zr[1 * SCRSTR];
                const float zy  = zr[2 * SCRSTR];
                const float zt  = zr[3 * SCRSTR];
                const float zxx = zr[4 * SCRSTR];
                const float zyy = zr[5 * SCRSTR];
                float s, sp, spp; swish_derivs(z, s, sp, spp);
                zr[0]          = s;
                zr[1 * SCRSTR] = sp * zx;
                zr[2 * SCRSTR] = sp * zy;
                zr[3 * SCRSTR] = sp * zt;
                zr[4 * SCRSTR] = fmaf(spp, zx * zx, sp * zxx);
                zr[5 * SCRSTR] = fmaf(spp, zy * zy, sp * zyy);
            }
            __syncthreads();
        }
    }

    // ---------------- final layer (256 -> 2) from fp32 scr + residual -------
    float au = 0.0f, av = 0.0f;
    if (tid < MROWS) {
        const int row = tid;
        const float4* sr = reinterpret_cast<const float4*>(scr + row * SCRSTR);
        const float2* w2p = reinterpret_cast<const float2*>(W4);
        #pragma unroll 1
        for (int i = 0; i < 64; i++) {
            const float4 v = sr[i];
            const float2 wa = w2p[i * 4 + 0];
            const float2 wb = w2p[i * 4 + 1];
            const float2 wc = w2p[i * 4 + 2];
            const float2 wd = w2p[i * 4 + 3];
            au = fmaf(v.x, wa.x, fmaf(v.y, wb.x, fmaf(v.z, wc.x, fmaf(v.w, wd.x, au))));
            av = fmaf(v.x, wa.y, fmaf(v.y, wb.y, fmaf(v.z, wc.y, fmaf(v.w, wd.y, av))));
        }
    }
    __syncthreads();   // all scr reads complete before overwriting
    if (tid < MROWS) {
        scr[tid * 2 + 0] = au;
        scr[tid * 2 + 1] = av;
    }
    __syncthreads();

    if (tid < NPTS) {
        const int idx = base + tid;
        if (idx < N) {
            const int rb = tid * 6;
            const float u   = scr[(rb + 0) * 2 + 0] + b4[0];
            const float v   = scr[(rb + 0) * 2 + 1] + b4[1];
            const float u_x = scr[(rb + 1) * 2 + 0], v_x = scr[(rb + 1) * 2 + 1];
            const float u_y = scr[(rb + 2) * 2 + 0], v_y = scr[(rb + 2) * 2 + 1];
            const float u_t = scr[(rb + 3) * 2 + 0], v_t = scr[(rb + 3) * 2 + 1];
            const float uxx = scr[(rb + 4) * 2 + 0], vxx = scr[(rb + 4) * 2 + 1];
            const float uyy = scr[(rb + 5) * 2 + 0], vyy = scr[(rb + 5) * 2 + 1];
            const float nv = nu[idx];
            out[idx * 2 + 0] = u_t + u * u_x + v * u_y - nv * (uxx + uyy);
            out[idx * 2 + 1] = v_t + u * v_x + v * v_y - nv * (vxx + vyy);
        }
    }
}

extern "C" void kernel_launch(void* const* d_in, const int* in_sizes, int n_in,
                              void* d_out, int out_size) {
    const float* x  = (const float*)d_in[0];
    const float* y  = (const float*)d_in[1];
    const float* t  = (const float*)d_in[2];
    const float* nu = (const float*)d_in[3];
    const float* W0 = (const float*)d_in[4];
    const float* b0 = (const float*)d_in[5];
    const float* W1 = (const float*)d_in[6];
    const float* b1 = (const float*)d_in[7];
    const float* W2 = (const float*)d_in[8];
    const float* b2 = (const float*)d_in[9];
    const float* W3 = (const float*)d_in[10];
    const float* b3 = (const float*)d_in[11];
    const float* W4 = (const float*)d_in[12];
    const float* b4 = (const float*)d_in[13];
    float* out = (float*)d_out;

    const int N = in_sizes[0];

    cudaFuncSetAttribute(pinn_mma_kernel, cudaFuncAttributeMaxDynamicSharedMemorySize, SMEM_BYTES);

    prep_kernel<<<(3 * 65536 + 255) / 256, 256>>>(W1, W2, W3);

    const int blocks = (N + NPTS - 1) / NPTS;
    pinn_mma_kernel<<<blocks, TPB, SMEM_BYTES>>>(x, y, t, nu, W0, b0,
                                                 b1, b2, b3, W4, b4, out, N);
}

// round 15
// speedup vs baseline: 1.3736x; 1.1260x over previous
#include <cuda_runtime.h>
#include <cuda_bf16.h>
#include <cstdint>

#define NPTS 8            // points per CTA
#define TPB 256           // 8 warps

// ---- SMEM layout (byte offsets from 1024-aligned base) ----
// A' transposed [k][m], m-row = ch*8 + p  (6 ch x 8 pts = 48 rows), 112B row stride
#define ASTR_T  112
#define OFF_AHI 0         // 256*112 = 28672
#define OFF_ALO 28672     // ends 57344
#define OFF_B   57344     // 3 x chunk buffers of 16896 B
#define BUF_BYTES 16896
#define BSPL    8448
#define BSTR    528
#define OFF_RED 57344     // final-reduction scratch (aliases buffers; used only at the end)
#define OFF_MBAR 108032
#define SMEM_BYTES (108032 + 64 + 1024)   // -> 2 CTAs/SM

// weights staged in EXACT smem-image layout: [layer][chunk16][split2][16 rows x 528B]
__device__ __align__(16) unsigned char g_Wstage[3 * 16 * BUF_BYTES];

#define LDSM4T(R0,R1,R2,R3,ADDR) \
  asm volatile("ldmatrix.sync.aligned.m8n8.x4.trans.shared.b16 {%0,%1,%2,%3}, [%4];" \
    : "=r"(R0),"=r"(R1),"=r"(R2),"=r"(R3) : "r"(ADDR))
#define MMA_BF16(D,A0,A1,A2,A3,B0,B1) \
  asm volatile("mma.sync.aligned.m16n8k16.row.col.f32.bf16.bf16.f32 " \
    "{%0,%1,%2,%3},{%4,%5,%6,%7},{%8,%9},{%0,%1,%2,%3};" \
    : "+f"(D[0]),"+f"(D[1]),"+f"(D[2]),"+f"(D[3]) \
    : "r"(A0),"r"(A1),"r"(A2),"r"(A3),"r"(B0),"r"(B1))

#define MBAR_INIT(ADDR, CNT) \
  asm volatile("mbarrier.init.shared.b64 [%0], %1;" :: "r"(ADDR), "r"(CNT) : "memory")
#define MBAR_EXPECT_TX(ADDR, BYTES) \
  asm volatile("mbarrier.arrive.expect_tx.shared.b64 _, [%0], %1;" :: "r"(ADDR), "r"(BYTES) : "memory")
#define MBAR_ARRIVE(ADDR) \
  asm volatile("mbarrier.arrive.shared.b64 _, [%0];" :: "r"(ADDR) : "memory")
#define BULK_LOAD(DST, SRC, BYTES, MBAR) \
  asm volatile("cp.async.bulk.shared::cluster.global.mbarrier::complete_tx::bytes [%0], [%1], %2, [%3];" \
    :: "r"(DST), "l"(SRC), "r"(BYTES), "r"(MBAR) : "memory")
#define MBAR_WAIT(ADDR, PAR) do { \
    asm volatile( \
        "{\n\t.reg .pred P;\n" \
        "WL%=:\n\t" \
        "mbarrier.try_wait.parity.acquire.cta.shared::cta.b64 P, [%0], %1, 0x989680;\n\t" \
        "@P bra WD%=;\n\t" \
        "bra WL%=;\n" \
        "WD%=:\n\t}" \
        :: "r"(ADDR), "r"(PAR) : "memory"); \
} while (0)

__device__ __forceinline__ uint32_t smem_u32(const void* p) {
    uint32_t a;
    asm("{ .reg .u64 t; cvta.to.shared.u64 t, %1; cvt.u32.u64 %0, t; }" : "=r"(a) : "l"(p));
    return a;
}

__device__ __forceinline__ void swish_derivs(float z, float& s, float& sp, float& spp) {
    float sig = 1.0f / (1.0f + __expf(-z));
    float om  = 1.0f - sig;
    s   = z * sig;
    sp  = sig * (1.0f + z * om);
    spp = sig * om * (2.0f + z * (1.0f - 2.0f * sig));
}

__device__ __forceinline__ void split_pack(float a, float b, uint32_t& hp, uint32_t& lp) {
    __nv_bfloat16 ha = __float2bfloat16(a);
    __nv_bfloat16 hb = __float2bfloat16(b);
    __nv_bfloat16 la = __float2bfloat16(a - __bfloat162float(ha));
    __nv_bfloat16 lb = __float2bfloat16(b - __bfloat162float(hb));
    uint16_t uha = *reinterpret_cast<uint16_t*>(&ha);
    uint16_t uhb = *reinterpret_cast<uint16_t*>(&hb);
    uint16_t ula = *reinterpret_cast<uint16_t*>(&la);
    uint16_t ulb = *reinterpret_cast<uint16_t*>(&lb);
    hp = (uint32_t)uha | ((uint32_t)uhb << 16);
    lp = (uint32_t)ula | ((uint32_t)ulb << 16);
}

// single-value hi/lo store into A' at column k, m-row = ch*8+p
__device__ __forceinline__ void storeA1(char* sm, int k, int p, int ch, float v) {
    const uint32_t o = (uint32_t)k * ASTR_T + (uint32_t)(ch * 8 + p) * 2;
    __nv_bfloat16 hi = __float2bfloat16(v);
    __nv_bfloat16 lo = __float2bfloat16(v - __bfloat162float(hi));
    *reinterpret_cast<uint16_t*>(sm + OFF_AHI + o) = *reinterpret_cast<uint16_t*>(&hi);
    *reinterpret_cast<uint16_t*>(sm + OFF_ALO + o) = *reinterpret_cast<uint16_t*>(&lo);
}

// ---- prep: split W1..W3 into bf16 hi/lo, stored in smem-image chunk layout ----
__global__ void prep_kernel(const float* __restrict__ W1, const float* __restrict__ W2,
                            const float* __restrict__ W3) {
    int i = blockIdx.x * blockDim.x + threadIdx.x;
    if (i >= 3 * 65536) return;
    const int layer = i >> 16;
    const int r = i & 65535;
    const int k = r >> 8;
    const int n = r & 255;
    const float* W = (layer == 0) ? W1 : (layer == 1) ? W2 : W3;
    const float w = W[r];
    __nv_bfloat16 hi = __float2bfloat16(w);
    float rem = w - __bfloat162float(hi);
    __nv_bfloat16 lo = __float2bfloat16(rem);
    const int chunk = k >> 4;
    const int kr = k & 15;
    const size_t base = (size_t)(layer * 16 + chunk) * BUF_BYTES + (size_t)kr * BSTR + (size_t)n * 2;
    *reinterpret_cast<__nv_bfloat16*>(g_Wstage + base) = hi;
    *reinterpret_cast<__nv_bfloat16*>(g_Wstage + base + BSPL) = lo;
}

// producer: fill global-chunk g into buffer g%3 (waits buffer-empty for rounds >= 1)
__device__ __forceinline__ void issue_fill(uint32_t sbase, int g) {
    const uint32_t mbf = sbase + OFF_MBAR + (uint32_t)(g % 3) * 8;
    const uint32_t mbe = sbase + OFF_MBAR + 24 + (uint32_t)(g % 3) * 8;
    const int r = g / 3;
    if (r >= 1) MBAR_WAIT(mbe, (uint32_t)((r - 1) & 1));
    MBAR_EXPECT_TX(mbf, (uint32_t)BUF_BYTES);
    BULK_LOAD(sbase + OFF_B + (uint32_t)(g % 3) * BUF_BYTES,
              (const void*)(g_Wstage + (size_t)g * BUF_BYTES),
              (uint32_t)BUF_BYTES, mbf);
}

// ---- main kernel ----
__global__ __launch_bounds__(TPB, 2)
void pinn_mma_kernel(
    const float* __restrict__ x, const float* __restrict__ y,
    const float* __restrict__ t, const float* __restrict__ nu,
    const float* __restrict__ W0, const float* __restrict__ b0,
    const float* __restrict__ b1, const float* __restrict__ b2,
    const float* __restrict__ b3,
    const float* __restrict__ W4, const float* __restrict__ b4,
    float* __restrict__ out, int N)
{
    extern __shared__ char smem_raw[];
    const uint32_t rawa = smem_u32(smem_raw);
    const uint32_t sbase = (rawa + 1023u) & ~1023u;
    char* sm = smem_raw + (sbase - rawa);

    const int tid  = threadIdx.x;
    const int wid  = tid >> 5;
    const int lane = tid & 31;
    const int base = blockIdx.x * NPTS;

    const int n0 = wid * 32;         // N group start (32 cols per warp)
    const int nn = tid;              // neuron (0..255) for layer0
    const int pp = lane >> 2;        // this thread's point (epilogue)

    const uint32_t mbarF = sbase + OFF_MBAR;
    const uint32_t mbarE = sbase + OFF_MBAR + 24;

    if (tid == 0) {
        #pragma unroll
        for (int i = 0; i < 3; i++) {
            MBAR_INIT(mbarF + (uint32_t)i * 8, 1u);
            MBAR_INIT(mbarE + (uint32_t)i * 8, 8u);
        }
    }
    __syncthreads();

    if (tid == 0) { issue_fill(sbase, 0); issue_fill(sbase, 1); }

    // ---------------- layer 0: (4 -> 256) scalar -> A' row nn ----------------
    // row within A' column: m = ch*8 + p
    {
        const float w0 = W0[nn], w1 = W0[256 + nn], w2 = W0[512 + nn], w3 = W0[768 + nn];
        const float bb = b0[nn];
        float o[6][NPTS];
        #pragma unroll
        for (int p = 0; p < NPTS; p++) {
            int idx = base + p; if (idx >= N) idx = N - 1;
            const float xs = x[idx];
            const float ys = y[idx];
            const float ts = 2.0f * t[idx] - 1.0f;
            const float ns = 2.0f * (nu[idx] - 0.01f) * (1.0f / 0.09f) - 1.0f;
            const float z  = fmaf(xs, w0, fmaf(ys, w1, fmaf(ts, w2, fmaf(ns, w3, bb))));
            const float zx = w0, zy = w1, zt = 2.0f * w2;
            float s, sp, spp; swish_derivs(z, s, sp, spp);
            o[0][p] = s;
            o[1][p] = sp * zx;
            o[2][p] = sp * zy;
            o[3][p] = sp * zt;
            o[4][p] = spp * zx * zx;
            o[5][p] = spp * zy * zy;
        }
        uint32_t h32[24], l32[24];
        #pragma unroll
        for (int ch = 0; ch < 6; ch++)
            #pragma unroll
            for (int q = 0; q < 4; q++)
                split_pack(o[ch][2 * q], o[ch][2 * q + 1], h32[ch * 4 + q], l32[ch * 4 + q]);
        uint4* dh = reinterpret_cast<uint4*>(sm + OFF_AHI + nn * ASTR_T);
        uint4* dl = reinterpret_cast<uint4*>(sm + OFF_ALO + nn * ASTR_T);
        #pragma unroll
        for (int j = 0; j < 6; j++) {
            dh[j] = make_uint4(h32[4*j], h32[4*j+1], h32[4*j+2], h32[4*j+3]);
            dl[j] = make_uint4(l32[4*j], l32[4*j+1], l32[4*j+2], l32[4*j+3]);
        }
    }
    __syncthreads();

    // final-layer partial accumulators (used at L==2)
    float part[12];   // [ch][uv]
    #pragma unroll
    for (int r = 0; r < 12; r++) part[r] = 0.0f;

    // ---------------- 3 hidden layers: bf16-split GEMM + register swish -----
    #pragma unroll 1
    for (int L = 0; L < 3; L++) {
        const float* __restrict__ bptr = (L == 0) ? b1 : (L == 1) ? b2 : b3;

        float acc[3][4][4];
        #pragma unroll
        for (int m = 0; m < 3; m++)
            #pragma unroll
            for (int nt = 0; nt < 4; nt++)
                #pragma unroll
                for (int r = 0; r < 4; r++) acc[m][nt][r] = 0.0f;

        #pragma unroll 1
        for (int c = 0; c < 16; c++) {
            const int g = L * 16 + c;
            if (tid == 0 && g + 2 < 48) issue_fill(sbase, g + 2);

            MBAR_WAIT(mbarF + (uint32_t)(g % 3) * 8, (uint32_t)((g / 3) & 1));

            const uint32_t bufb = sbase + OFF_B + (uint32_t)(g % 3) * BUF_BYTES;

            uint32_t Bh[8], Bl[8];
            #pragma unroll
            for (int q = 0; q < 2; q++) {
                const uint32_t roff = (uint32_t)(lane & 15) * BSTR
                                    + (uint32_t)(n0 + q * 16 + (lane >> 4) * 8) * 2;
                LDSM4T(Bh[q * 4], Bh[q * 4 + 1], Bh[q * 4 + 2], Bh[q * 4 + 3], bufb + roff);
                LDSM4T(Bl[q * 4], Bl[q * 4 + 1], Bl[q * 4 + 2], Bl[q * 4 + 3], bufb + BSPL + roff);
            }
            if (lane == 0) MBAR_ARRIVE(mbarE + (uint32_t)(g % 3) * 8);

            uint32_t Ah[3][4];
            uint32_t aroff[3];
            const uint32_t krow = (uint32_t)(c * 16 + (lane & 7) + ((lane >> 4) << 3));
            const uint32_t mcol = (uint32_t)(((lane >> 3) & 1) * 8) * 2;
            #pragma unroll
            for (int m = 0; m < 3; m++) {
                aroff[m] = krow * ASTR_T + (uint32_t)(m * 16) * 2 + mcol;
                LDSM4T(Ah[m][0], Ah[m][1], Ah[m][2], Ah[m][3], sbase + OFF_AHI + aroff[m]);
            }
            #pragma unroll
            for (int m = 0; m < 3; m++)
                #pragma unroll
                for (int nt = 0; nt < 4; nt++)
                    MMA_BF16(acc[m][nt], Ah[m][0], Ah[m][1], Ah[m][2], Ah[m][3],
                             Bh[nt * 2], Bh[nt * 2 + 1]);
            #pragma unroll
            for (int m = 0; m < 3; m++)
                #pragma unroll
                for (int nt = 0; nt < 4; nt++)
                    MMA_BF16(acc[m][nt], Ah[m][0], Ah[m][1], Ah[m][2], Ah[m][3],
                             Bl[nt * 2], Bl[nt * 2 + 1]);
            uint32_t Al[3][4];
            #pragma unroll
            for (int m = 0; m < 3; m++)
                LDSM4T(Al[m][0], Al[m][1], Al[m][2], Al[m][3], sbase + OFF_ALO + aroff[m]);
            #pragma unroll
            for (int m = 0; m < 3; m++)
                #pragma unroll
                for (int nt = 0; nt < 4; nt++)
                    MMA_BF16(acc[m][nt], Al[m][0], Al[m][1], Al[m][2], Al[m][3],
                             Bh[nt * 2], Bh[nt * 2 + 1]);
        }
        __syncthreads();   // all warps done reading A' before anyone rewrites it

        // ---- register epilogue: swish chain straight from accumulators ----
        // thread owns point pp, cols k = n0 + nt*8 + (lane&3)*2 + j
        #pragma unroll
        for (int nt = 0; nt < 4; nt++) {
            const int k0 = n0 + nt * 8 + (lane & 3) * 2;
            const float2 bv = *reinterpret_cast<const float2*>(&bptr[k0]);
            #pragma unroll
            for (int j = 0; j < 2; j++) {
                const int k = k0 + j;
                const float z   = acc[0][nt][j] + (j ? bv.y : bv.x);
                const float zx  = acc[0][nt][2 + j];
                const float zy  = acc[1][nt][j];
                const float zt  = acc[1][nt][2 + j];
                const float zxx = acc[2][nt][j];
                const float zyy = acc[2][nt][2 + j];
                float s, sp, spp; swish_derivs(z, s, sp, spp);
                const float o0 = s;
                const float o1 = sp * zx;
                const float o2 = sp * zy;
                const float o3 = sp * zt;
                const float o4 = fmaf(spp, zx * zx, sp * zxx);
                const float o5 = fmaf(spp, zy * zy, sp * zyy);
                if (L < 2) {
                    storeA1(sm, k, pp, 0, o0);
                    storeA1(sm, k, pp, 1, o1);
                    storeA1(sm, k, pp, 2, o2);
                    storeA1(sm, k, pp, 3, o3);
                    storeA1(sm, k, pp, 4, o4);
                    storeA1(sm, k, pp, 5, o5);
                } else {
                    // final layer: accumulate partial dots with W4 directly
                    const float2 w = *reinterpret_cast<const float2*>(&W4[2 * k]);
                    part[0]  = fmaf(o0, w.x, part[0]);   part[1]  = fmaf(o0, w.y, part[1]);
                    part[2]  = fmaf(o1, w.x, part[2]);   part[3]  = fmaf(o1, w.y, part[3]);
                    part[4]  = fmaf(o2, w.x, part[4]);   part[5]  = fmaf(o2, w.y, part[5]);
                    part[6]  = fmaf(o3, w.x, part[6]);   part[7]  = fmaf(o3, w.y, part[7]);
                    part[8]  = fmaf(o4, w.x, part[8]);   part[9]  = fmaf(o4, w.y, part[9]);
                    part[10] = fmaf(o5, w.x, part[10]);  part[11] = fmaf(o5, w.y, part[11]);
                }
            }
        }
        __syncthreads();   // A' writes visible (L<2); buffers reusable as scratch (L==2)
    }

    // ---------------- final reduction: quad shuffles + smem ------------------
    #pragma unroll
    for (int r = 0; r < 12; r++) {
        part[r] += __shfl_xor_sync(0xffffffffu, part[r], 1);
        part[r] += __shfl_xor_sync(0xffffffffu, part[r], 2);
    }
    float* red = reinterpret_cast<float*>(sm + OFF_RED);   // [8 warps][8 pts][12]
    if ((lane & 3) == 0) {
        float* dst = red + (wid * 8 + pp) * 12;
        #pragma unroll
        for (int r = 0; r < 12; r++) dst[r] = part[r];
    }
    __syncthreads();

    if (tid < 96) {
        const int p = tid / 12, r = tid % 12;
        float s = 0.0f;
        #pragma unroll
        for (int w = 0; w < 8; w++) s += red[(w * 8 + p) * 12 + r];
        red[768 + p * 12 + r] = s;
    }
    __syncthreads();

    if (tid < NPTS) {
        const int idx = base + tid;
        if (idx < N) {
            const float* rp = red + 768 + tid * 12;
            const float u   = rp[0] + b4[0];
            const float v   = rp[1] + b4[1];
            const float u_x = rp[2],  v_x = rp[3];
            const float u_y = rp[4],  v_y = rp[5];
            const float u_t = rp[6],  v_t = rp[7];
            const float uxx = rp[8],  vxx = rp[9];
            const float uyy = rp[10], vyy = rp[11];
            const float nv = nu[idx];
            out[idx * 2 + 0] = u_t + u * u_x + v * u_y - nv * (uxx + uyy);
            out[idx * 2 + 1] = v_t + u * v_x + v * v_y - nv * (vxx + vyy);
        }
    }
}

extern "C" void kernel_launch(void* const* d_in, const int* in_sizes, int n_in,
                              void* d_out, int out_size) {
    const float* x  = (const float*)d_in[0];
    const float* y  = (const float*)d_in[1];
    const float* t  = (const float*)d_in[2];
    const float* nu = (const float*)d_in[3];
    const float* W0 = (const float*)d_in[4];
    const float* b0 = (const float*)d_in[5];
    const float* W1 = (const float*)d_in[6];
    const float* b1 = (const float*)d_in[7];
    const float* W2 = (const float*)d_in[8];
    const float* b2 = (const float*)d_in[9];
    const float* W3 = (const float*)d_in[10];
    const float* b3 = (const float*)d_in[11];
    const float* W4 = (const float*)d_in[12];
    const float* b4 = (const float*)d_in[13];
    float* out = (float*)d_out;

    const int N = in_sizes[0];

    cudaFuncSetAttribute(pinn_mma_kernel, cudaFuncAttributeMaxDynamicSharedMemorySize, SMEM_BYTES);

    prep_kernel<<<(3 * 65536 + 255) / 256, 256>>>(W1, W2, W3);

    const int blocks = (N + NPTS - 1) / NPTS;
    pinn_mma_kernel<<<blocks, TPB, SMEM_BYTES>>>(x, y, t, nu, W0, b0,
                                                 b1, b2, b3, W4, b4, out, N);
}